// round 13
// baseline (speedup 1.0000x reference)
#include <cuda_runtime.h>
#include <cuda_fp16.h>
#include <cstdint>

// Problem constants (fixed by the dataset)
#define B_TOTAL   32768
#define N_IN      128
#define NLAYERS   8
#define WID       256
#define KK        16
#define T         64          // batch rows per block; lane carries a row PAIR (half2)
#define NTHREADS  512         // 16 warps -> 128 regs/thread for ILP
#define NWARPS    16
#define NBLOCKS   (B_TOTAL / T)          // 512
#define SPLIT     1408        // cols < SPLIT live in SMEM; cols >= SPLIT in global scratch
#define NCOLS_ALL 1920        // 128 + 7*256 (layer-7 out never re-gathered)
#define TBL       (NLAYERS * WID * KK)   // 32768 table entries

// SMEM layout (dynamic, 231,424 B total):
//   [0      , 180224) s_hist     : __half2 [1408][32]  (history, transposed, row pairs)
//   [180224 , 205824) table buf 0: idx 16K | wt(half) 8K | bias 1K  (25,600 B)
//   [205824 , 231424) table buf 1: same
#define OFF_TBL0   180224
#define TBLBUF     25600
#define TB_IDX     0
#define TB_WT      16384
#define TB_BIAS    24576
#define SMEM_BYTES (OFF_TBL0 + 2 * TBLBUF)

// Global scratch for evicted history cols [1408, 1920): [block][col'][32 pairs]
#define SC_COLS (NCOLS_ALL - SPLIT)      // 512
__device__ __half2 g_scratch[(size_t)NBLOCKS * SC_COLS * (T / 2)];   // 32 MB
// Preprocessed tables (built by prep_kernel each replay)
__device__ __half  g_wh  [TBL];          // weights as plain half (lane-select at use)
__device__ int     g_idxb[TBL];          // edge_idx * 128 (byte offset into history)

extern __shared__ unsigned char smem_raw[];

__device__ __forceinline__ void cp16(unsigned int saddr, const void* gptr) {
    asm volatile("cp.async.cg.shared.global [%0], [%1], 16;\n"
                 :: "r"(saddr), "l"(gptr));
}

// fast sigmoid via EX2+RCP (tanh.approx measured 60% SLOWER on sm_103a — do not use)
__device__ __forceinline__ float2 sigmoid2(float2 pre) {
    float2 s;
    s.x = __fdividef(1.0f, 1.0f + __expf(-pre.x));
    s.y = __fdividef(1.0f, 1.0f + __expf(-pre.y));
    return s;
}

// ---- prep: weights -> half, indices -> byte offsets ----
__global__ void prep_kernel(const float* __restrict__ weights,
                            const int*   __restrict__ edge_idx) {
    int i = blockIdx.x * blockDim.x + threadIdx.x;   // exactly TBL threads
    g_wh  [i] = __float2half(weights[i]);
    g_idxb[i] = edge_idx[i] << 7;                    // *128 bytes per history col
}

// ---- dual-w 16-edge dots (w0 and w1 = w0+16 interleaved for 2x ILP), pure-SMEM ----
// weights: sw2[w*8 + j] holds halves for edges 2j, 2j+1 (lane-selected)
__device__ __forceinline__ void pre_smem2(const char* __restrict__ hlane,
                                          const int4* __restrict__ si4,
                                          const __half2* __restrict__ sw2,
                                          float bias0, float bias1,
                                          int w0, int w1,
                                          float2& out0, float2& out1) {
    __half2 z = __float2half2_rn(0.0f);
    __half2 a0 = z, a1 = z, a2 = z, a3 = z;   // w0 chains
    __half2 b0 = z, b1 = z, b2 = z, b3 = z;   // w1 chains
    #pragma unroll
    for (int g = 0; g < 4; ++g) {
        int4    iva = si4[w0 * 4 + g];
        int4    ivb = si4[w1 * 4 + g];
        __half2 wa0 = sw2[w0 * 8 + g * 2];
        __half2 wa1 = sw2[w0 * 8 + g * 2 + 1];
        __half2 wb0 = sw2[w1 * 8 + g * 2];
        __half2 wb1 = sw2[w1 * 8 + g * 2 + 1];
        a0 = __hfma2(*(const __half2*)(hlane + iva.x), __low2half2 (wa0), a0);
        b0 = __hfma2(*(const __half2*)(hlane + ivb.x), __low2half2 (wb0), b0);
        a1 = __hfma2(*(const __half2*)(hlane + iva.y), __high2half2(wa0), a1);
        b1 = __hfma2(*(const __half2*)(hlane + ivb.y), __high2half2(wb0), b1);
        a2 = __hfma2(*(const __half2*)(hlane + iva.z), __low2half2 (wa1), a2);
        b2 = __hfma2(*(const __half2*)(hlane + ivb.z), __low2half2 (wb1), b2);
        a3 = __hfma2(*(const __half2*)(hlane + iva.w), __high2half2(wa1), a3);
        b3 = __hfma2(*(const __half2*)(hlane + ivb.w), __high2half2(wb1), b3);
    }
    float2 p0 = __half22float2(a0), p1 = __half22float2(a1);
    float2 p2 = __half22float2(a2), p3 = __half22float2(a3);
    float2 q0 = __half22float2(b0), q1 = __half22float2(b1);
    float2 q2 = __half22float2(b2), q3 = __half22float2(b3);
    out0 = make_float2(bias0 + (p0.x + p1.x) + (p2.x + p3.x),
                       bias0 + (p0.y + p1.y) + (p2.y + p3.y));
    out1 = make_float2(bias1 + (q0.x + q1.x) + (q2.x + q3.x),
                       bias1 + (q0.y + q1.y) + (q2.y + q3.y));
}

// ---- dual-w, mixed smem/scratch path (layers 6,7) ----
__device__ __forceinline__ void pre_mixed2(const char* __restrict__ hlane,
                                           const char* __restrict__ glane,
                                           const int4* __restrict__ si4,
                                           const __half2* __restrict__ sw2,
                                           float bias0, float bias1,
                                           int w0, int w1,
                                           float2& out0, float2& out1) {
    const int LIM = SPLIT * 128;
    __half2 z = __float2half2_rn(0.0f);
    __half2 a0 = z, a1 = z, a2 = z, a3 = z;
    __half2 b0 = z, b1 = z, b2 = z, b3 = z;
    #pragma unroll
    for (int g = 0; g < 4; ++g) {
        int4    iva = si4[w0 * 4 + g];
        int4    ivb = si4[w1 * 4 + g];
        __half2 wa0 = sw2[w0 * 8 + g * 2];
        __half2 wa1 = sw2[w0 * 8 + g * 2 + 1];
        __half2 wb0 = sw2[w1 * 8 + g * 2];
        __half2 wb1 = sw2[w1 * 8 + g * 2 + 1];
        const char* pax = ((iva.x < LIM) ? hlane : glane) + iva.x;
        const char* pbx = ((ivb.x < LIM) ? hlane : glane) + ivb.x;
        const char* pay = ((iva.y < LIM) ? hlane : glane) + iva.y;
        const char* pby = ((ivb.y < LIM) ? hlane : glane) + ivb.y;
        const char* paz = ((iva.z < LIM) ? hlane : glane) + iva.z;
        const char* pbz = ((ivb.z < LIM) ? hlane : glane) + ivb.z;
        const char* paw = ((iva.w < LIM) ? hlane : glane) + iva.w;
        const char* pbw = ((ivb.w < LIM) ? hlane : glane) + ivb.w;
        a0 = __hfma2(*(const __half2*)pax, __low2half2 (wa0), a0);
        b0 = __hfma2(*(const __half2*)pbx, __low2half2 (wb0), b0);
        a1 = __hfma2(*(const __half2*)pay, __high2half2(wa0), a1);
        b1 = __hfma2(*(const __half2*)pby, __high2half2(wb0), b1);
        a2 = __hfma2(*(const __half2*)paz, __low2half2 (wa1), a2);
        b2 = __hfma2(*(const __half2*)pbz, __low2half2 (wb1), b2);
        a3 = __hfma2(*(const __half2*)paw, __high2half2(wa1), a3);
        b3 = __hfma2(*(const __half2*)pbw, __high2half2(wb1), b3);
    }
    float2 p0 = __half22float2(a0), p1 = __half22float2(a1);
    float2 p2 = __half22float2(a2), p3 = __half22float2(a3);
    float2 q0 = __half22float2(b0), q1 = __half22float2(b1);
    float2 q2 = __half22float2(b2), q3 = __half22float2(b3);
    out0 = make_float2(bias0 + (p0.x + p1.x) + (p2.x + p3.x),
                       bias0 + (p0.y + p1.y) + (p2.y + p3.y));
    out1 = make_float2(bias1 + (q0.x + q1.x) + (q2.x + q3.x),
                       bias1 + (q0.y + q1.y) + (q2.y + q3.y));
}

__global__ __launch_bounds__(NTHREADS, 1)
void ffn_edge_kernel(const float* __restrict__ inputs,    // [B, 128]
                     const float* __restrict__ biases,    // [L, W]
                     float*       __restrict__ out)       // [B, W]
{
    __half2* s_h2 = (__half2*)smem_raw;

    unsigned int s_base = (unsigned int)__cvta_generic_to_shared(smem_raw);

    const int tid  = threadIdx.x;
    const int lane = tid & 31;
    const int wid  = tid >> 5;
    const int row0 = blockIdx.x * T;

    __half2* gblk = g_scratch + (size_t)blockIdx.x * (SC_COLS * (T / 2));
    // per-lane base pointers (generic space); offsets from tables are bytes
    const char* hlane = (const char*)s_h2 + lane * 4;
    const char* glane = (const char*)gblk + lane * 4 - SPLIT * 128;

    // ---- Kick off layer-0 table prefetch into buf 0 (overlaps input staging) ----
    {
        unsigned int tb = s_base + OFF_TBL0;
        cp16(tb + TB_IDX + tid * 16,          (const char*)g_idxb + tid * 16);          // 8 KB
        cp16(tb + TB_IDX + (tid + 512) * 16,  (const char*)g_idxb + (tid + 512) * 16);  // 8 KB
        cp16(tb + TB_WT  + tid * 16,          (const char*)g_wh   + tid * 16);          // 8 KB
        if (tid < 64) cp16(tb + TB_BIAS + tid * 16, (const char*)biases + tid * 16);    // 1 KB
        asm volatile("cp.async.commit_group;\n");
    }

    // ---- Stage input [64][128] fp32 coalesced into pad-132 buffer.
    // Overlays hist bytes [16384, 50176) = cols 128..392 (< SPLIT, not yet written).
    float* s_stage = (float*)(smem_raw + 16384);
    {
        const float4* in4 = (const float4*)(inputs + (size_t)row0 * N_IN);
        #pragma unroll 1
        for (int i = tid; i < T * (N_IN / 4); i += NTHREADS) {
            int r  = i >> 5;            // 32 float4 per row
            int c4 = i & 31;
            float4 v = in4[i];
            float* dst = s_stage + r * 132 + c4 * 4;
            dst[0] = v.x; dst[1] = v.y; dst[2] = v.z; dst[3] = v.w;
        }
    }
    __syncthreads();
    // ---- Transpose-convert input into s_h2[col][pair]: lo = row 2p, hi = row 2p+1
    #pragma unroll 1
    for (int i = tid; i < N_IN * 32; i += NTHREADS) {
        int col = i >> 5;
        int p   = i & 31;
        float lo = s_stage[(2 * p)     * 132 + col];
        float hi = s_stage[(2 * p + 1) * 132 + col];
        s_h2[col * 32 + p] = __floats2half2_rn(lo, hi);
    }

    // ---- 8 layers; tables DOUBLE-buffered; dual-w per iteration (ILP) ----
    int ncols = N_IN;
    #pragma unroll 1
    for (int l = 0; l < NLAYERS; ++l) {
        asm volatile("cp.async.wait_group 0;\n");
        __syncthreads();   // tables buf[l&1] ready + prior-layer history (smem+gmem) visible

        // issue next layer's prefetch into the OTHER buffer (no one reads it now)
        if (l < NLAYERS - 1) {
            unsigned int tb = s_base + OFF_TBL0 + ((l + 1) & 1) * TBLBUF;
            const char* gi = (const char*)(g_idxb + (size_t)(l + 1) * WID * KK);
            const char* gw = (const char*)(g_wh   + (size_t)(l + 1) * WID * KK);
            cp16(tb + TB_IDX + tid * 16,         gi + tid * 16);
            cp16(tb + TB_IDX + (tid + 512) * 16, gi + (tid + 512) * 16);
            cp16(tb + TB_WT  + tid * 16,         gw + tid * 16);
            if (tid < 64)
                cp16(tb + TB_BIAS + tid * 16,
                     (const char*)(biases + (size_t)(l + 1) * WID) + tid * 16);
            asm volatile("cp.async.commit_group;\n");
        }

        const unsigned char* tbl = smem_raw + OFF_TBL0 + (l & 1) * TBLBUF;
        const int4*    si4 = (const int4*)   (tbl + TB_IDX);
        const __half2* sw2 = (const __half2*)(tbl + TB_WT);
        const float*   sb  = (const float*)  (tbl + TB_BIAS);

        if (l < 5) {
            // pure-SMEM gathers AND writes (layer 4 writes cols <= 1407 < SPLIT)
            #pragma unroll 1
            for (int w = wid; w < WID; w += 2 * NWARPS) {
                int w1 = w + NWARPS;
                float2 pre0, pre1;
                pre_smem2(hlane, si4, sw2, sb[w], sb[w1], w, w1, pre0, pre1);
                float2 sg0 = sigmoid2(pre0);
                float2 sg1 = sigmoid2(pre1);
                s_h2[(ncols + w)  * 32 + lane] = __floats2half2_rn(sg0.x, sg0.y);
                s_h2[(ncols + w1) * 32 + lane] = __floats2half2_rn(sg1.x, sg1.y);
            }
        } else if (l == 5) {
            // gathers pure-SMEM (cols < 1408); outputs (1408..1663) all to scratch
            #pragma unroll 1
            for (int w = wid; w < WID; w += 2 * NWARPS) {
                int w1 = w + NWARPS;
                float2 pre0, pre1;
                pre_smem2(hlane, si4, sw2, sb[w], sb[w1], w, w1, pre0, pre1);
                float2 sg0 = sigmoid2(pre0);
                float2 sg1 = sigmoid2(pre1);
                gblk[(ncols + w  - SPLIT) * 32 + lane] = __floats2half2_rn(sg0.x, sg0.y);
                gblk[(ncols + w1 - SPLIT) * 32 + lane] = __floats2half2_rn(sg1.x, sg1.y);
            }
        } else if (l == 6) {
            // mixed gathers; outputs (1664..1919) to scratch
            #pragma unroll 1
            for (int w = wid; w < WID; w += 2 * NWARPS) {
                int w1 = w + NWARPS;
                float2 pre0, pre1;
                pre_mixed2(hlane, glane, si4, sw2, sb[w], sb[w1], w, w1, pre0, pre1);
                float2 sg0 = sigmoid2(pre0);
                float2 sg1 = sigmoid2(pre1);
                gblk[(ncols + w  - SPLIT) * 32 + lane] = __floats2half2_rn(sg0.x, sg0.y);
                gblk[(ncols + w1 - SPLIT) * 32 + lane] = __floats2half2_rn(sg1.x, sg1.y);
            }
        } else {
            // layer 7: mixed gathers; fp32 result straight to GMEM
            float* og = out + ((size_t)row0 + 2 * lane) * WID;
            #pragma unroll 1
            for (int w = wid; w < WID; w += 2 * NWARPS) {
                int w1 = w + NWARPS;
                float2 pre0, pre1;
                pre_mixed2(hlane, glane, si4, sw2, sb[w], sb[w1], w, w1, pre0, pre1);
                float2 sg0 = sigmoid2(pre0);
                float2 sg1 = sigmoid2(pre1);
                og[w]        = sg0.x;   // row 2*lane
                og[w  + WID] = sg0.y;   // row 2*lane + 1
                og[w1]       = sg1.x;
                og[w1 + WID] = sg1.y;
            }
        }
        ncols += WID;
    }
}

extern "C" void kernel_launch(void* const* d_in, const int* in_sizes, int n_in,
                              void* d_out, int out_size)
{
    (void)in_sizes; (void)n_in; (void)out_size;
    const float* inputs   = (const float*)d_in[0];
    const float* weights  = (const float*)d_in[1];
    const float* biases   = (const float*)d_in[2];
    const int*   edge_idx = (const int*)  d_in[3];
    float*       out      = (float*)d_out;

    cudaFuncSetAttribute(ffn_edge_kernel,
                         cudaFuncAttributeMaxDynamicSharedMemorySize, SMEM_BYTES);

    prep_kernel<<<TBL / 256, 256>>>(weights, edge_idx);

    dim3 grid(NBLOCKS);        // 512 blocks of 64 rows
    dim3 block(NTHREADS);      // 512 threads, 16 warps, ~128 regs/thread
    ffn_edge_kernel<<<grid, block, SMEM_BYTES>>>(inputs, biases, out);
}

// round 14
// speedup vs baseline: 1.0246x; 1.0246x over previous
#include <cuda_runtime.h>
#include <cuda_fp16.h>
#include <cstdint>

// Problem constants (fixed by the dataset)
#define B_TOTAL   32768
#define N_IN      128
#define NLAYERS   8
#define WID       256
#define KK        16
#define T         64          // batch rows per block; lane carries a row PAIR (half2)
#define NTHREADS  1024
#define NWARPS    32
#define NBLOCKS   (B_TOTAL / T)          // 512
#define SPLIT     1408        // cols < SPLIT live in SMEM; cols >= SPLIT in global scratch
#define NCOLS_ALL 1920        // 128 + 7*256 (layer-7 out never re-gathered)
#define TBL       (NLAYERS * WID * KK)   // 32768 table entries

// SMEM layout (dynamic, 231,424 B total):
//   [0      , 180224) s_hist     : __half2 [1408][32]  (history, transposed, row pairs)
//   [180224 , 205824) table buf 0: idx 16K | wt(half) 8K | bias 1K  (25,600 B)
//   [205824 , 231424) table buf 1: same
#define OFF_TBL0   180224
#define TBLBUF     25600
#define TB_IDX     0
#define TB_WT      16384
#define TB_BIAS    24576
#define SMEM_BYTES (OFF_TBL0 + 2 * TBLBUF)

// Global scratch for evicted history cols [1408, 1920): [block][col'][32 pairs]
#define SC_COLS (NCOLS_ALL - SPLIT)      // 512
__device__ __half2 g_scratch[(size_t)NBLOCKS * SC_COLS * (T / 2)];   // 32 MB
// Preprocessed tables (built by prep_kernel each replay)
__device__ __half  g_wh  [TBL];          // weights as plain half (lane-select at use)
__device__ int     g_idxb[TBL];          // edge_idx * 128 (byte offset into history)

extern __shared__ unsigned char smem_raw[];

__device__ __forceinline__ void cp16(unsigned int saddr, const void* gptr) {
    asm volatile("cp.async.cg.shared.global [%0], [%1], 16;\n"
                 :: "r"(saddr), "l"(gptr));
}

// fast sigmoid via EX2+RCP (tanh.approx measured 60% SLOWER on sm_103a — do not use)
__device__ __forceinline__ float2 sigmoid2(float2 pre) {
    float2 s;
    s.x = __fdividef(1.0f, 1.0f + __expf(-pre.x));
    s.y = __fdividef(1.0f, 1.0f + __expf(-pre.y));
    return s;
}

// ---- prep: weights -> half, indices -> byte offsets ----
__global__ void prep_kernel(const float* __restrict__ weights,
                            const int*   __restrict__ edge_idx) {
    int i = blockIdx.x * blockDim.x + threadIdx.x;   // exactly TBL threads
    g_wh  [i] = __float2half(weights[i]);
    g_idxb[i] = edge_idx[i] << 7;                    // *128 bytes per history col
}

// 16-edge dot -> half2 partial sum (tree-reduced), all offsets < SPLIT*128 (layers 0..5)
// weights: sw2[w*8 + j] holds halves for edges 2j, 2j+1 (lane-selected)
__device__ __forceinline__ __half2 pre_smem(const char* __restrict__ hlane,
                                            const int4* __restrict__ si4,
                                            const __half2* __restrict__ sw2,
                                            int w) {
    __half2 z = __float2half2_rn(0.0f);
    __half2 acc0 = z, acc1 = z, acc2 = z, acc3 = z;
    #pragma unroll
    for (int g = 0; g < 4; ++g) {
        int4    iv  = si4[w * 4 + g];
        __half2 wp0 = sw2[w * 8 + g * 2];       // edges 4g, 4g+1
        __half2 wp1 = sw2[w * 8 + g * 2 + 1];   // edges 4g+2, 4g+3
        acc0 = __hfma2(*(const __half2*)(hlane + iv.x), __low2half2 (wp0), acc0);
        acc1 = __hfma2(*(const __half2*)(hlane + iv.y), __high2half2(wp0), acc1);
        acc2 = __hfma2(*(const __half2*)(hlane + iv.z), __low2half2 (wp1), acc2);
        acc3 = __hfma2(*(const __half2*)(hlane + iv.w), __high2half2(wp1), acc3);
    }
    return __hadd2(__hadd2(acc0, acc1), __hadd2(acc2, acc3));
}

// layers 6,7: offsets may reach scratch -> branchless pointer select
__device__ __forceinline__ __half2 pre_mixed(const char* __restrict__ hlane,
                                             const char* __restrict__ glane,
                                             const int4* __restrict__ si4,
                                             const __half2* __restrict__ sw2,
                                             int w) {
    const int LIM = SPLIT * 128;
    __half2 z = __float2half2_rn(0.0f);
    __half2 acc0 = z, acc1 = z, acc2 = z, acc3 = z;
    #pragma unroll
    for (int g = 0; g < 4; ++g) {
        int4    iv  = si4[w * 4 + g];
        __half2 wp0 = sw2[w * 8 + g * 2];
        __half2 wp1 = sw2[w * 8 + g * 2 + 1];
        const char* px = ((iv.x < LIM) ? hlane : glane) + iv.x;
        const char* py = ((iv.y < LIM) ? hlane : glane) + iv.y;
        const char* pz = ((iv.z < LIM) ? hlane : glane) + iv.z;
        const char* pw = ((iv.w < LIM) ? hlane : glane) + iv.w;
        acc0 = __hfma2(*(const __half2*)px, __low2half2 (wp0), acc0);
        acc1 = __hfma2(*(const __half2*)py, __high2half2(wp0), acc1);
        acc2 = __hfma2(*(const __half2*)pz, __low2half2 (wp1), acc2);
        acc3 = __hfma2(*(const __half2*)pw, __high2half2(wp1), acc3);
    }
    return __hadd2(__hadd2(acc0, acc1), __hadd2(acc2, acc3));
}

// epilogue: half2 partial sum + fp32 bias -> sigmoid (fp32)
__device__ __forceinline__ float2 finish(__half2 hs, float bias) {
    float2 pre = __half22float2(hs);
    pre.x += bias;
    pre.y += bias;
    return sigmoid2(pre);
}

__global__ __launch_bounds__(NTHREADS, 1)
void ffn_edge_kernel(const float* __restrict__ inputs,    // [B, 128]
                     const float* __restrict__ biases,    // [L, W]
                     float*       __restrict__ out)       // [B, W]
{
    __half2* s_h2 = (__half2*)smem_raw;

    unsigned int s_base = (unsigned int)__cvta_generic_to_shared(smem_raw);

    const int tid  = threadIdx.x;
    const int lane = tid & 31;
    const int wid  = tid >> 5;
    const int row0 = blockIdx.x * T;

    __half2* gblk = g_scratch + (size_t)blockIdx.x * (SC_COLS * (T / 2));
    // per-lane base pointers (generic space); offsets from tables are bytes
    const char* hlane = (const char*)s_h2 + lane * 4;
    const char* glane = (const char*)gblk + lane * 4 - SPLIT * 128;

    // ---- Kick off layer-0 table prefetch into buf 0 (overlaps input staging) ----
    {
        unsigned int tb = s_base + OFF_TBL0;
        cp16(tb + TB_IDX + tid * 16, (const char*)g_idxb + tid * 16);           // 16 KB
        if (tid < 512) cp16(tb + TB_WT + tid * 16, (const char*)g_wh + tid * 16); // 8 KB
        if (tid < 64)  cp16(tb + TB_BIAS + tid * 16, (const char*)biases + tid * 16); // 1 KB
        asm volatile("cp.async.commit_group;\n");
    }

    // ---- Stage input [64][128] fp32 coalesced into pad-132 buffer.
    // Overlays hist bytes [16384, 50176) = cols 128..392 (< SPLIT, not yet written).
    float* s_stage = (float*)(smem_raw + 16384);
    {
        const float4* in4 = (const float4*)(inputs + (size_t)row0 * N_IN);
        #pragma unroll 1
        for (int i = tid; i < T * (N_IN / 4); i += NTHREADS) {
            int r  = i >> 5;            // 32 float4 per row
            int c4 = i & 31;
            float4 v = in4[i];
            float* dst = s_stage + r * 132 + c4 * 4;
            dst[0] = v.x; dst[1] = v.y; dst[2] = v.z; dst[3] = v.w;
        }
    }
    __syncthreads();
    // ---- Transpose-convert input into s_h2[col][pair]: lo = row 2p, hi = row 2p+1
    #pragma unroll 1
    for (int i = tid; i < N_IN * 32; i += NTHREADS) {
        int col = i >> 5;
        int p   = i & 31;
        float lo = s_stage[(2 * p)     * 132 + col];
        float hi = s_stage[(2 * p + 1) * 132 + col];
        s_h2[col * 32 + p] = __floats2half2_rn(lo, hi);
    }

    // ---- 8 layers; tables DOUBLE-buffered: prefetch next layer at top, overlap compute ----
    int ncols = N_IN;
    #pragma unroll 1
    for (int l = 0; l < NLAYERS; ++l) {
        asm volatile("cp.async.wait_group 0;\n");
        __syncthreads();   // tables buf[l&1] ready + prior-layer history (smem+gmem) visible

        // issue next layer's prefetch into the OTHER buffer (no one reads it now)
        if (l < NLAYERS - 1) {
            unsigned int tb = s_base + OFF_TBL0 + ((l + 1) & 1) * TBLBUF;
            const char* gi = (const char*)(g_idxb + (size_t)(l + 1) * WID * KK);
            const char* gw = (const char*)(g_wh   + (size_t)(l + 1) * WID * KK);
            cp16(tb + TB_IDX + tid * 16, gi + tid * 16);
            if (tid < 512) cp16(tb + TB_WT + tid * 16, gw + tid * 16);
            if (tid < 64)
                cp16(tb + TB_BIAS + tid * 16,
                     (const char*)(biases + (size_t)(l + 1) * WID) + tid * 16);
            asm volatile("cp.async.commit_group;\n");
        }

        const unsigned char* tbl = smem_raw + OFF_TBL0 + (l & 1) * TBLBUF;
        const int4*    si4 = (const int4*)   (tbl + TB_IDX);
        const __half2* sw2 = (const __half2*)(tbl + TB_WT);
        const float*   sb  = (const float*)  (tbl + TB_BIAS);

        if (l < 5) {
            // pure-SMEM gathers AND writes (layer 4 writes cols <= 1407 < SPLIT)
            #pragma unroll 2
            for (int w = wid; w < WID; w += NWARPS) {
                float2 sg = finish(pre_smem(hlane, si4, sw2, w), sb[w]);
                s_h2[(ncols + w) * 32 + lane] = __floats2half2_rn(sg.x, sg.y);
            }
        } else if (l == 5) {
            // gathers pure-SMEM (cols < 1408); outputs (1408..1663) all to scratch
            #pragma unroll 2
            for (int w = wid; w < WID; w += NWARPS) {
                float2 sg = finish(pre_smem(hlane, si4, sw2, w), sb[w]);
                gblk[(ncols + w - SPLIT) * 32 + lane] = __floats2half2_rn(sg.x, sg.y);
            }
        } else if (l == 6) {
            // mixed gathers; outputs (1664..1919) to scratch
            #pragma unroll 1
            for (int w = wid; w < WID; w += NWARPS) {
                float2 sg = finish(pre_mixed(hlane, glane, si4, sw2, w), sb[w]);
                gblk[(ncols + w - SPLIT) * 32 + lane] = __floats2half2_rn(sg.x, sg.y);
            }
        } else {
            // layer 7: mixed gathers; fp32 result straight to GMEM
            float* og = out + ((size_t)row0 + 2 * lane) * WID;
            #pragma unroll 1
            for (int w = wid; w < WID; w += NWARPS) {
                float2 sg = finish(pre_mixed(hlane, glane, si4, sw2, w), sb[w]);
                og[w]       = sg.x;   // row 2*lane
                og[w + WID] = sg.y;   // row 2*lane + 1
            }
        }
        ncols += WID;
    }
}

extern "C" void kernel_launch(void* const* d_in, const int* in_sizes, int n_in,
                              void* d_out, int out_size)
{
    (void)in_sizes; (void)n_in; (void)out_size;
    const float* inputs   = (const float*)d_in[0];
    const float* weights  = (const float*)d_in[1];
    const float* biases   = (const float*)d_in[2];
    const int*   edge_idx = (const int*)  d_in[3];
    float*       out      = (float*)d_out;

    cudaFuncSetAttribute(ffn_edge_kernel,
                         cudaFuncAttributeMaxDynamicSharedMemorySize, SMEM_BYTES);

    prep_kernel<<<TBL / 256, 256>>>(weights, edge_idx);

    dim3 grid(NBLOCKS);        // 512 blocks of 64 rows
    dim3 block(NTHREADS);
    ffn_edge_kernel<<<grid, block, SMEM_BYTES>>>(inputs, biases, out);
}

// round 16
// speedup vs baseline: 1.0357x; 1.0108x over previous
#include <cuda_runtime.h>
#include <cuda_fp16.h>
#include <cstdint>

// Problem constants (fixed by the dataset)
#define B_TOTAL   32768
#define N_IN      128
#define NLAYERS   8
#define WID       256
#define KK        16
#define T         64          // batch rows per block; lane carries a row PAIR (half2)
#define NTHREADS  1024
#define NWARPS    32
#define NBLOCKS   (B_TOTAL / T)          // 512
#define SPLIT     1408        // cols < SPLIT live in SMEM; cols >= SPLIT in global scratch
#define NCOLS_ALL 1920        // 128 + 7*256 (layer-7 out never re-gathered)
#define TBL       (NLAYERS * WID * KK)   // 32768 table entries

// SMEM layout (dynamic, 231,424 B total):
//   [0      , 180224) s_hist     : __half2 [1408][32]  (history, transposed, row pairs)
//   [180224 , 205824) table buf 0: idx 16K | wt(half) 8K | bias 1K  (25,600 B)
//   [205824 , 231424) table buf 1: same
#define OFF_TBL0   180224
#define TBLBUF     25600
#define TB_IDX     0
#define TB_WT      16384
#define TB_BIAS    24576
#define SMEM_BYTES (OFF_TBL0 + 2 * TBLBUF)

// Global scratch for evicted history cols [1408, 1920): [block][col'][32 pairs]
#define SC_COLS (NCOLS_ALL - SPLIT)      // 512
__device__ __half2 g_scratch[(size_t)NBLOCKS * SC_COLS * (T / 2)];   // 32 MB
// Preprocessed tables (built by prep_kernel each replay)
__device__ __half  g_wh  [TBL];          // weights as plain half (16 per w = 32B, vector-loaded)
__device__ int     g_idxb[TBL];          // edge_idx * 128 (byte offset into history)

extern __shared__ unsigned char smem_raw[];

__device__ __forceinline__ void cp16(unsigned int saddr, const void* gptr) {
    asm volatile("cp.async.cg.shared.global [%0], [%1], 16;\n"
                 :: "r"(saddr), "l"(gptr));
}

__device__ __forceinline__ __half2 u2h2(unsigned int u) {
    __half2 h;
    *(unsigned int*)&h = u;
    return h;
}

// fast sigmoid via EX2+RCP (tanh.approx measured 60% SLOWER on sm_103a — do not use)
__device__ __forceinline__ float2 sigmoid2(float2 pre) {
    float2 s;
    s.x = __fdividef(1.0f, 1.0f + __expf(-pre.x));
    s.y = __fdividef(1.0f, 1.0f + __expf(-pre.y));
    return s;
}

// ---- prep: weights -> half, indices -> byte offsets ----
__global__ void prep_kernel(const float* __restrict__ weights,
                            const int*   __restrict__ edge_idx) {
    int i = blockIdx.x * blockDim.x + threadIdx.x;   // exactly TBL threads
    g_wh  [i] = __float2half(weights[i]);
    g_idxb[i] = edge_idx[i] << 7;                    // *128 bytes per history col
}

// 16-edge dot -> half2 partial sum (tree-reduced), all offsets < SPLIT*128 (layers 0..5)
// weights: swq[w*2], swq[w*2+1] hold 16 halves; each uint lane = one packed __half2 pair
__device__ __forceinline__ __half2 pre_smem(const char* __restrict__ hlane,
                                            const int4* __restrict__ si4,
                                            const uint4* __restrict__ swq,
                                            int w) {
    uint4 wq0 = swq[w * 2];       // edges 0..7   (pairs: x=01 y=23 z=45 w=67)
    uint4 wq1 = swq[w * 2 + 1];   // edges 8..15
    __half2 z = __float2half2_rn(0.0f);
    __half2 acc0 = z, acc1 = z, acc2 = z, acc3 = z;
    #pragma unroll
    for (int g = 0; g < 4; ++g) {
        int4 iv = si4[w * 4 + g];
        unsigned int p0 = (g == 0) ? wq0.x : (g == 1) ? wq0.z : (g == 2) ? wq1.x : wq1.z;
        unsigned int p1 = (g == 0) ? wq0.y : (g == 1) ? wq0.w : (g == 2) ? wq1.y : wq1.w;
        __half2 wp0 = u2h2(p0);   // weights for edges 4g, 4g+1
        __half2 wp1 = u2h2(p1);   // weights for edges 4g+2, 4g+3
        acc0 = __hfma2(*(const __half2*)(hlane + iv.x), __low2half2 (wp0), acc0);
        acc1 = __hfma2(*(const __half2*)(hlane + iv.y), __high2half2(wp0), acc1);
        acc2 = __hfma2(*(const __half2*)(hlane + iv.z), __low2half2 (wp1), acc2);
        acc3 = __hfma2(*(const __half2*)(hlane + iv.w), __high2half2(wp1), acc3);
    }
    return __hadd2(__hadd2(acc0, acc1), __hadd2(acc2, acc3));
}

// layers 6,7: offsets may reach scratch -> branchless pointer select
__device__ __forceinline__ __half2 pre_mixed(const char* __restrict__ hlane,
                                             const char* __restrict__ glane,
                                             const int4* __restrict__ si4,
                                             const uint4* __restrict__ swq,
                                             int w) {
    const int LIM = SPLIT * 128;
    uint4 wq0 = swq[w * 2];
    uint4 wq1 = swq[w * 2 + 1];
    __half2 z = __float2half2_rn(0.0f);
    __half2 acc0 = z, acc1 = z, acc2 = z, acc3 = z;
    #pragma unroll
    for (int g = 0; g < 4; ++g) {
        int4 iv = si4[w * 4 + g];
        unsigned int p0 = (g == 0) ? wq0.x : (g == 1) ? wq0.z : (g == 2) ? wq1.x : wq1.z;
        unsigned int p1 = (g == 0) ? wq0.y : (g == 1) ? wq0.w : (g == 2) ? wq1.y : wq1.w;
        __half2 wp0 = u2h2(p0);
        __half2 wp1 = u2h2(p1);
        const char* px = ((iv.x < LIM) ? hlane : glane) + iv.x;
        const char* py = ((iv.y < LIM) ? hlane : glane) + iv.y;
        const char* pz = ((iv.z < LIM) ? hlane : glane) + iv.z;
        const char* pw = ((iv.w < LIM) ? hlane : glane) + iv.w;
        acc0 = __hfma2(*(const __half2*)px, __low2half2 (wp0), acc0);
        acc1 = __hfma2(*(const __half2*)py, __high2half2(wp0), acc1);
        acc2 = __hfma2(*(const __half2*)pz, __low2half2 (wp1), acc2);
        acc3 = __hfma2(*(const __half2*)pw, __high2half2(wp1), acc3);
    }
    return __hadd2(__hadd2(acc0, acc1), __hadd2(acc2, acc3));
}

// epilogue: half2 partial sum + fp32 bias -> sigmoid (fp32)
__device__ __forceinline__ float2 finish(__half2 hs, float bias) {
    float2 pre = __half22float2(hs);
    pre.x += bias;
    pre.y += bias;
    return sigmoid2(pre);
}

__global__ __launch_bounds__(NTHREADS, 1)
void ffn_edge_kernel(const float* __restrict__ inputs,    // [B, 128]
                     const float* __restrict__ biases,    // [L, W]
                     float*       __restrict__ out)       // [B, W]
{
    __half2* s_h2 = (__half2*)smem_raw;

    unsigned int s_base = (unsigned int)__cvta_generic_to_shared(smem_raw);

    const int tid  = threadIdx.x;
    const int lane = tid & 31;
    const int wid  = tid >> 5;
    const int row0 = blockIdx.x * T;

    __half2* gblk = g_scratch + (size_t)blockIdx.x * (SC_COLS * (T / 2));
    // per-lane base pointers (generic space); offsets from tables are bytes
    const char* hlane = (const char*)s_h2 + lane * 4;
    const char* glane = (const char*)gblk + lane * 4 - SPLIT * 128;

    // ---- Kick off layer-0 table prefetch into buf 0 (overlaps input staging) ----
    {
        unsigned int tb = s_base + OFF_TBL0;
        cp16(tb + TB_IDX + tid * 16, (const char*)g_idxb + tid * 16);           // 16 KB
        if (tid < 512) cp16(tb + TB_WT + tid * 16, (const char*)g_wh + tid * 16); // 8 KB
        if (tid < 64)  cp16(tb + TB_BIAS + tid * 16, (const char*)biases + tid * 16); // 1 KB
        asm volatile("cp.async.commit_group;\n");
    }

    // ---- Stage input [64][128] fp32 coalesced into pad-132 buffer.
    // Overlays hist bytes [16384, 50176) = cols 128..392 (< SPLIT, not yet written).
    float* s_stage = (float*)(smem_raw + 16384);
    {
        const float4* in4 = (const float4*)(inputs + (size_t)row0 * N_IN);
        #pragma unroll 1
        for (int i = tid; i < T * (N_IN / 4); i += NTHREADS) {
            int r  = i >> 5;            // 32 float4 per row
            int c4 = i & 31;
            float4 v = in4[i];
            float* dst = s_stage + r * 132 + c4 * 4;
            dst[0] = v.x; dst[1] = v.y; dst[2] = v.z; dst[3] = v.w;
        }
    }
    __syncthreads();
    // ---- Transpose-convert input into s_h2[col][pair]: lo = row 2p, hi = row 2p+1
    #pragma unroll 1
    for (int i = tid; i < N_IN * 32; i += NTHREADS) {
        int col = i >> 5;
        int p   = i & 31;
        float lo = s_stage[(2 * p)     * 132 + col];
        float hi = s_stage[(2 * p + 1) * 132 + col];
        s_h2[col * 32 + p] = __floats2half2_rn(lo, hi);
    }

    // ---- 8 layers; tables DOUBLE-buffered: prefetch next layer at top, overlap compute ----
    int ncols = N_IN;
    #pragma unroll 1
    for (int l = 0; l < NLAYERS; ++l) {
        asm volatile("cp.async.wait_group 0;\n");
        __syncthreads();   // tables buf[l&1] ready + prior-layer history (smem+gmem) visible

        // issue next layer's prefetch into the OTHER buffer (no one reads it now)
        if (l < NLAYERS - 1) {
            unsigned int tb = s_base + OFF_TBL0 + ((l + 1) & 1) * TBLBUF;
            const char* gi = (const char*)(g_idxb + (size_t)(l + 1) * WID * KK);
            const char* gw = (const char*)(g_wh   + (size_t)(l + 1) * WID * KK);
            cp16(tb + TB_IDX + tid * 16, gi + tid * 16);
            if (tid < 512) cp16(tb + TB_WT + tid * 16, gw + tid * 16);
            if (tid < 64)
                cp16(tb + TB_BIAS + tid * 16,
                     (const char*)(biases + (size_t)(l + 1) * WID) + tid * 16);
            asm volatile("cp.async.commit_group;\n");
        }

        const unsigned char* tbl = smem_raw + OFF_TBL0 + (l & 1) * TBLBUF;
        const int4*  si4 = (const int4*) (tbl + TB_IDX);
        const uint4* swq = (const uint4*)(tbl + TB_WT);
        const float* sb  = (const float*)(tbl + TB_BIAS);

        if (l < 5) {
            // pure-SMEM gathers AND writes (layer 4 writes cols <= 1407 < SPLIT)
            #pragma unroll 2
            for (int w = wid; w < WID; w += NWARPS) {
                float2 sg = finish(pre_smem(hlane, si4, swq, w), sb[w]);
                s_h2[(ncols + w) * 32 + lane] = __floats2half2_rn(sg.x, sg.y);
            }
        } else if (l == 5) {
            // gathers pure-SMEM (cols < 1408); outputs (1408..1663) all to scratch
            #pragma unroll 2
            for (int w = wid; w < WID; w += NWARPS) {
                float2 sg = finish(pre_smem(hlane, si4, swq, w), sb[w]);
                gblk[(ncols + w - SPLIT) * 32 + lane] = __floats2half2_rn(sg.x, sg.y);
            }
        } else if (l == 6) {
            // mixed gathers; outputs (1664..1919) to scratch
            #pragma unroll 1
            for (int w = wid; w < WID; w += NWARPS) {
                float2 sg = finish(pre_mixed(hlane, glane, si4, swq, w), sb[w]);
                gblk[(ncols + w - SPLIT) * 32 + lane] = __floats2half2_rn(sg.x, sg.y);
            }
        } else {
            // layer 7: mixed gathers; fp32 result straight to GMEM
            float* og = out + ((size_t)row0 + 2 * lane) * WID;
            #pragma unroll 1
            for (int w = wid; w < WID; w += NWARPS) {
                float2 sg = finish(pre_mixed(hlane, glane, si4, swq, w), sb[w]);
                og[w]       = sg.x;   // row 2*lane
                og[w + WID] = sg.y;   // row 2*lane + 1
            }
        }
        ncols += WID;
    }
}

extern "C" void kernel_launch(void* const* d_in, const int* in_sizes, int n_in,
                              void* d_out, int out_size)
{
    (void)in_sizes; (void)n_in; (void)out_size;
    const float* inputs   = (const float*)d_in[0];
    const float* weights  = (const float*)d_in[1];
    const float* biases   = (const float*)d_in[2];
    const int*   edge_idx = (const int*)  d_in[3];
    float*       out      = (float*)d_out;

    cudaFuncSetAttribute(ffn_edge_kernel,
                         cudaFuncAttributeMaxDynamicSharedMemorySize, SMEM_BYTES);

    prep_kernel<<<TBL / 256, 256>>>(weights, edge_idx);

    dim3 grid(NBLOCKS);        // 512 blocks of 64 rows
    dim3 block(NTHREADS);
    ffn_edge_kernel<<<grid, block, SMEM_BYTES>>>(inputs, biases, out);
}